// round 2
// baseline (speedup 1.0000x reference)
#include <cuda_runtime.h>
#include <math.h>

// Problem constants (fixed by setup_inputs)
#define DIN   4096
#define DOUT  4096
#define RNK   64
#define NEXP  16
#define K2DIM 1024          // NEXP * RNK
#define MAXT  8192
#define SCALING 0.5f        // 32/64

// Scratch (device globals; no allocation allowed in kernel_launch)
__device__ float g_Acat[128 * DIN];      // rows 0..63 = A, 64..79 = router_w, 80..127 = 0
__device__ float g_H[MAXT * 128];        // per-token [h(64) | logits(16) | pad]
__device__ float g_G[MAXT * K2DIM];      // dense combine*h
__device__ float g_B2[DOUT * K2DIM];     // B2[o][e*64+r] = SCALING * B[e][o][r]

// ---------------------------------------------------------------------------
// prep: build g_Acat (padded [A; router_w]) and g_B2 (scaled transpose of B)
// ---------------------------------------------------------------------------
__global__ void prep_kernel(const float* __restrict__ A,
                            const float* __restrict__ router_w,
                            const float* __restrict__ B)
{
    const int n1 = 128 * DIN;
    const int n2 = DOUT * K2DIM;
    for (int idx = blockIdx.x * blockDim.x + threadIdx.x;
         idx < n1 + n2;
         idx += gridDim.x * blockDim.x)
    {
        if (idx < n1) {
            int row = idx / DIN, col = idx - row * DIN;
            float v = 0.0f;
            if (row < RNK)            v = A[row * DIN + col];
            else if (row < RNK+NEXP)  v = router_w[(row - RNK) * DIN + col];
            g_Acat[idx] = v;
        } else {
            int j  = idx - n1;
            int o  = j / K2DIM;
            int er = j - o * K2DIM;
            int e  = er >> 6, r = er & 63;
            g_B2[j] = SCALING * B[((size_t)e * DOUT + o) * RNK + r];
        }
    }
}

// ---------------------------------------------------------------------------
// route: per-token softmax over 16 logits, top-2, normalize, build dense G row
// one warp per token
// ---------------------------------------------------------------------------
__global__ void route_kernel(int T)
{
    int warp = (blockIdx.x * blockDim.x + threadIdx.x) >> 5;
    int lane = threadIdx.x & 31;
    if (warp >= T) return;

    const float* h = g_H + (size_t)warp * 128;

    float logit = (lane < NEXP) ? h[64 + lane] : -1e30f;
    float m = logit;
    #pragma unroll
    for (int off = 16; off; off >>= 1)
        m = fmaxf(m, __shfl_xor_sync(0xffffffffu, m, off));
    float p = (lane < NEXP) ? expf(logit - m) : 0.0f;
    float s = p;
    #pragma unroll
    for (int off = 16; off; off >>= 1)
        s += __shfl_xor_sync(0xffffffffu, s, off);
    p /= s;

    // top-1 (ties -> lower index)
    float v1 = p; int i1 = lane;
    #pragma unroll
    for (int off = 16; off; off >>= 1) {
        float ov = __shfl_xor_sync(0xffffffffu, v1, off);
        int   oi = __shfl_xor_sync(0xffffffffu, i1, off);
        if (ov > v1 || (ov == v1 && oi < i1)) { v1 = ov; i1 = oi; }
    }
    // top-2 (exclude i1)
    float v2 = (lane == i1) ? -1.0f : p; int i2 = lane;
    #pragma unroll
    for (int off = 16; off; off >>= 1) {
        float ov = __shfl_xor_sync(0xffffffffu, v2, off);
        int   oi = __shfl_xor_sync(0xffffffffu, i2, off);
        if (ov > v2 || (ov == v2 && oi < i2)) { v2 = ov; i2 = oi; }
    }

    float snorm = v1 + v2 + 1e-6f;
    float w0 = v1 / snorm, w1 = v2 / snorm;

    float* Grow = g_G + (size_t)warp * K2DIM;
    for (int j = lane; j < K2DIM; j += 32) {
        int e = j >> 6, r = j & 63;
        float val = 0.0f;
        if (e == i1)      val = w0 * h[r];
        else if (e == i2) val = w1 * h[r];
        Grow[j] = val;
    }
}

// ---------------------------------------------------------------------------
// Fused tiled fp32 GEMM: C[m, n] = sum_k Amat[m,k]*Bmat[n,k]
//                               (+ sum_k2 A2[m,k2]*B2mat[n,k2]) (+ bias[n])
// 128x128 tile, BK=8, 256 threads, 8x8 per thread.
// ---------------------------------------------------------------------------
__global__ void __launch_bounds__(256, 2)
gemm_fused(const float* __restrict__ Amat, const float* __restrict__ Bmat, int K1,
           const float* __restrict__ A2,   const float* __restrict__ B2mat, int K2,
           const float* __restrict__ bias,
           float* __restrict__ C, int ldc)
{
    __shared__ float As[8][128];
    __shared__ float Bs[8][128];

    const int m0  = blockIdx.y * 128;
    const int n0  = blockIdx.x * 128;
    const int tid = threadIdx.x;
    const int tx  = tid & 15;       // 0..15  (N dir)
    const int ty  = tid >> 4;       // 0..15  (M dir)
    const int lrow = tid >> 1;      // 0..127
    const int lcol = (tid & 1) << 2;// 0 or 4

    float acc[8][8];
    #pragma unroll
    for (int i = 0; i < 8; i++)
        #pragma unroll
        for (int j = 0; j < 8; j++) acc[i][j] = 0.0f;

    // ---- K-loop 1: base operands ----
    {
        const float* ap = Amat + (size_t)(m0 + lrow) * K1 + lcol;
        const float* bp = Bmat + (size_t)(n0 + lrow) * K1 + lcol;
        for (int k0 = 0; k0 < K1; k0 += 8) {
            float4 av = *(const float4*)(ap + k0);
            float4 bv = *(const float4*)(bp + k0);
            As[lcol+0][lrow] = av.x; As[lcol+1][lrow] = av.y;
            As[lcol+2][lrow] = av.z; As[lcol+3][lrow] = av.w;
            Bs[lcol+0][lrow] = bv.x; Bs[lcol+1][lrow] = bv.y;
            Bs[lcol+2][lrow] = bv.z; Bs[lcol+3][lrow] = bv.w;
            __syncthreads();
            #pragma unroll
            for (int kk = 0; kk < 8; kk++) {
                float af[8], bf[8];
                *(float4*)(af)   = *(const float4*)&As[kk][ty*8];
                *(float4*)(af+4) = *(const float4*)&As[kk][ty*8+4];
                *(float4*)(bf)   = *(const float4*)&Bs[kk][tx*8];
                *(float4*)(bf+4) = *(const float4*)&Bs[kk][tx*8+4];
                #pragma unroll
                for (int i = 0; i < 8; i++)
                    #pragma unroll
                    for (int j = 0; j < 8; j++)
                        acc[i][j] = fmaf(af[i], bf[j], acc[i][j]);
            }
            __syncthreads();
        }
    }

    // ---- K-loop 2: LoRA delta operands (optional) ----
    if (A2 != nullptr) {
        const float* ap = A2    + (size_t)(m0 + lrow) * K2 + lcol;
        const float* bp = B2mat + (size_t)(n0 + lrow) * K2 + lcol;
        for (int k0 = 0; k0 < K2; k0 += 8) {
            float4 av = *(const float4*)(ap + k0);
            float4 bv = *(const float4*)(bp + k0);
            As[lcol+0][lrow] = av.x; As[lcol+1][lrow] = av.y;
            As[lcol+2][lrow] = av.z; As[lcol+3][lrow] = av.w;
            Bs[lcol+0][lrow] = bv.x; Bs[lcol+1][lrow] = bv.y;
            Bs[lcol+2][lrow] = bv.z; Bs[lcol+3][lrow] = bv.w;
            __syncthreads();
            #pragma unroll
            for (int kk = 0; kk < 8; kk++) {
                float af[8], bf[8];
                *(float4*)(af)   = *(const float4*)&As[kk][ty*8];
                *(float4*)(af+4) = *(const float4*)&As[kk][ty*8+4];
                *(float4*)(bf)   = *(const float4*)&Bs[kk][tx*8];
                *(float4*)(bf+4) = *(const float4*)&Bs[kk][tx*8+4];
                #pragma unroll
                for (int i = 0; i < 8; i++)
                    #pragma unroll
                    for (int j = 0; j < 8; j++)
                        acc[i][j] = fmaf(af[i], bf[j], acc[i][j]);
            }
            __syncthreads();
        }
    }

    // ---- epilogue ----
    #pragma unroll
    for (int i = 0; i < 8; i++) {
        int row = m0 + ty * 8 + i;
        float* cp = C + (size_t)row * ldc + n0 + tx * 8;
        float4 r0, r1;
        r0.x = acc[i][0]; r0.y = acc[i][1]; r0.z = acc[i][2]; r0.w = acc[i][3];
        r1.x = acc[i][4]; r1.y = acc[i][5]; r1.z = acc[i][6]; r1.w = acc[i][7];
        if (bias != nullptr) {
            const float* bp = bias + n0 + tx * 8;
            r0.x += bp[0]; r0.y += bp[1]; r0.z += bp[2]; r0.w += bp[3];
            r1.x += bp[4]; r1.y += bp[5]; r1.z += bp[6]; r1.w += bp[7];
        }
        *(float4*)cp       = r0;
        *(float4*)(cp + 4) = r1;
    }
}

// ---------------------------------------------------------------------------
extern "C" void kernel_launch(void* const* d_in, const int* in_sizes, int n_in,
                              void* d_out, int out_size)
{
    const float* x        = (const float*)d_in[0];  // [T, DIN]
    const float* base_w   = (const float*)d_in[1];  // [DOUT, DIN]
    const float* base_b   = (const float*)d_in[2];  // [DOUT]
    const float* A        = (const float*)d_in[3];  // [RNK, DIN]
    const float* B        = (const float*)d_in[4];  // [NEXP, DOUT, RNK]
    const float* router_w = (const float*)d_in[5];  // [NEXP, DIN]
    float* out = (float*)d_out;

    const int T = in_sizes[0] / DIN;                // 8192

    float *dAcat, *dH, *dG, *dB2;
    cudaGetSymbolAddress((void**)&dAcat, g_Acat);
    cudaGetSymbolAddress((void**)&dH,    g_H);
    cudaGetSymbolAddress((void**)&dG,    g_G);
    cudaGetSymbolAddress((void**)&dB2,   g_B2);

    // 1) prep: Acat + B2
    prep_kernel<<<1184, 256>>>(A, router_w, B);

    // 2) H = X @ Acat^T   (T x 128, logits in cols 64..79)
    {
        dim3 grid(1, T / 128);
        gemm_fused<<<grid, 256>>>(x, dAcat, DIN,
                                  nullptr, nullptr, 0,
                                  nullptr, dH, 128);
    }

    // 3) routing -> dense G
    route_kernel<<<(T + 7) / 8, 256>>>(T);

    // 4) out = X @ W^T + G @ B2^T + bias
    {
        dim3 grid(DOUT / 128, T / 128);
        gemm_fused<<<grid, 256>>>(x, base_w, DIN,
                                  dG, dB2, K2DIM,
                                  base_b, out, DOUT);
    }
}

// round 9
// speedup vs baseline: 2.8534x; 2.8534x over previous
#include <cuda_runtime.h>
#include <cuda_bf16.h>
#include <math.h>
#include <stdint.h>

// Problem constants
#define DIN   4096
#define DOUT  4096
#define RNK   64
#define NEXP  16
#define K2DIM 1024
#define MAXT  8192
#define SCALING 0.5f

#define STAGES 3
#define RS 72                 // smem row stride in bf16 elems (144 B) -> conflict-free
#define RSB (RS * 2)          // 144 bytes

// ---------------- scratch (device globals) ----------------
__device__ __align__(16) __nv_bfloat16 g_Xhi[MAXT * DIN];
__device__ __align__(16) __nv_bfloat16 g_Xlo[MAXT * DIN];
__device__ __align__(16) __nv_bfloat16 g_Whi[DOUT * DIN];
__device__ __align__(16) __nv_bfloat16 g_Wlo[DOUT * DIN];
__device__ __align__(16) __nv_bfloat16 g_AcatHi[128 * DIN];
__device__ __align__(16) __nv_bfloat16 g_AcatLo[128 * DIN];
__device__ __align__(16) __nv_bfloat16 g_Ghi[MAXT * K2DIM];
__device__ __align__(16) __nv_bfloat16 g_Glo[MAXT * K2DIM];
__device__ __align__(16) __nv_bfloat16 g_B2hi[DOUT * K2DIM];
__device__ __align__(16) __nv_bfloat16 g_B2lo[DOUT * K2DIM];
__device__ __align__(16) float g_H[MAXT * 128];

// ---------------- PTX helpers (baseline ISA only; no sm_103a-only ops) ------
__device__ __forceinline__ uint32_t smem_u32(const void* p) {
    uint32_t a;
    asm("{ .reg .u64 t; cvta.to.shared.u64 t, %1; cvt.u32.u64 %0, t; }" : "=r"(a) : "l"(p));
    return a;
}
__device__ __forceinline__ void cpasync16(uint32_t s, const void* g) {
    asm volatile("cp.async.cg.shared.global [%0], [%1], 16;" :: "r"(s), "l"(g));
}
__device__ __forceinline__ void cp_commit() { asm volatile("cp.async.commit_group;" ::: "memory"); }
template<int N> __device__ __forceinline__ void cp_wait() {
    asm volatile("cp.async.wait_group %0;" :: "n"(N) : "memory");
}
__device__ __forceinline__ void ldsm4(uint32_t& r0, uint32_t& r1, uint32_t& r2, uint32_t& r3, uint32_t a) {
    asm volatile("ldmatrix.sync.aligned.m8n8.x4.shared.b16 {%0,%1,%2,%3}, [%4];"
                 : "=r"(r0), "=r"(r1), "=r"(r2), "=r"(r3) : "r"(a));
}
__device__ __forceinline__ void mma16816(float* c,
                                         uint32_t a0, uint32_t a1, uint32_t a2, uint32_t a3,
                                         uint32_t b0, uint32_t b1) {
    asm volatile("mma.sync.aligned.m16n8k16.row.col.f32.bf16.bf16.f32 "
                 "{%0,%1,%2,%3},{%4,%5,%6,%7},{%8,%9},{%0,%1,%2,%3};"
                 : "+f"(c[0]), "+f"(c[1]), "+f"(c[2]), "+f"(c[3])
                 : "r"(a0), "r"(a1), "r"(a2), "r"(a3), "r"(b0), "r"(b1));
}

// ---------------- segment descriptor ----------------
struct Seg { const __nv_bfloat16* A; const __nv_bfloat16* B; int ktiles; int lda; int ldb; };
struct SegList { Seg s[6]; };

// ---------------- HMMA GEMM: C[M,N] = sum_seg Aseg@Bseg^T (+bias) ----------
// 128x128 block tile, BK=64, 3-stage cp.async ring, 8 warps (2x4), warp 64x32.
__global__ void __launch_bounds__(256)
gemm_hmma(SegList SL, int nseg, const float* __restrict__ bias,
          float* __restrict__ C, int ldc)
{
    extern __shared__ char smem[];
    const uint32_t sb = smem_u32(smem);
    const int tid  = threadIdx.x;
    const int wid  = tid >> 5, lane = tid & 31;
    const int m0   = blockIdx.y * 128;
    const int n0   = blockIdx.x * 128;
    const int wm   = (wid >> 2) * 64;   // warp m offset: 0 / 64
    const int wn   = (wid & 3) * 32;    // warp n offset: 0/32/64/96

    constexpr int ASTAGE = 128 * RSB;        // 18432 B
    constexpr int STAGEB = 2 * ASTAGE;       // A+B per stage

    float acc[4][4][4];
    #pragma unroll
    for (int i = 0; i < 4; i++)
        #pragma unroll
        for (int j = 0; j < 4; j++)
            #pragma unroll
            for (int q = 0; q < 4; q++) acc[i][j][q] = 0.0f;

    int total = 0;
    #pragma unroll
    for (int i = 0; i < 6; i++) if (i < nseg) total += SL.s[i].ktiles;

    // loader cursor (identical in all threads)
    int sg = 0, ktin = 0;
    auto load_stage = [&](int slot) {
        const Seg& S = SL.s[sg];
        const int lda2 = S.lda * 2, ldb2 = S.ldb * 2;
        const char* gA = (const char*)S.A + (size_t)m0 * lda2 + ktin * 128;
        const char* gB = (const char*)S.B + (size_t)n0 * ldb2 + ktin * 128;
        uint32_t sA = sb + slot * STAGEB;
        uint32_t sB = sA + ASTAGE;
        #pragma unroll
        for (int i = 0; i < 4; i++) {
            int ch  = tid + i * 256;
            int row = ch >> 3, cc = ch & 7;        // 128 rows x 8 chunks(16B)
            cpasync16(sA + row * RSB + cc * 16, gA + (size_t)row * lda2 + cc * 16);
            cpasync16(sB + row * RSB + cc * 16, gB + (size_t)row * ldb2 + cc * 16);
        }
        if (++ktin == S.ktiles) { ktin = 0; sg++; }
    };

    auto compute_stage = [&](int slot) {
        uint32_t sA = sb + slot * STAGEB;
        uint32_t sB = sA + ASTAGE;
        #pragma unroll
        for (int kc = 0; kc < 4; kc++) {       // 4 x k16 chunks
            uint32_t a[4][4];
            #pragma unroll
            for (int mt = 0; mt < 4; mt++) {
                int row = wm + mt * 16 + (lane & 15);
                uint32_t addr = sA + row * RSB + kc * 32 + (lane >> 4) * 16;
                ldsm4(a[mt][0], a[mt][1], a[mt][2], a[mt][3], addr);
            }
            uint32_t b[2][4];
            #pragma unroll
            for (int ng = 0; ng < 2; ng++) {
                int n = wn + ng * 16 + (lane & 7) + ((lane >> 4) << 3);
                uint32_t addr = sB + n * RSB + kc * 32 + ((lane >> 3) & 1) * 16;
                ldsm4(b[ng][0], b[ng][1], b[ng][2], b[ng][3], addr);
            }
            #pragma unroll
            for (int mt = 0; mt < 4; mt++)
                #pragma unroll
                for (int nt = 0; nt < 4; nt++)
                    mma16816(acc[mt][nt],
                             a[mt][0], a[mt][1], a[mt][2], a[mt][3],
                             b[nt >> 1][(nt & 1) * 2], b[nt >> 1][(nt & 1) * 2 + 1]);
        }
    };

    // prologue: fill stages 0..1
    load_stage(0); cp_commit();
    load_stage(1); cp_commit();

    for (int t = 0; t < total; t++) {
        cp_wait<1>();
        __syncthreads();
        if (t + 2 < total) load_stage((t + 2) % STAGES);
        cp_commit();
        compute_stage(t % STAGES);
    }

    // ---- epilogue ----
    #pragma unroll
    for (int mt = 0; mt < 4; mt++) {
        #pragma unroll
        for (int nt = 0; nt < 4; nt++) {
            int row = m0 + wm + mt * 16 + (lane >> 2);
            int col = n0 + wn + nt * 8 + (lane & 3) * 2;
            float b0 = 0.0f, b1 = 0.0f;
            if (bias) { b0 = __ldg(bias + col); b1 = __ldg(bias + col + 1); }
            float* c0 = C + (size_t)row * ldc + col;
            float* c1 = C + (size_t)(row + 8) * ldc + col;
            float2 v0 = make_float2(acc[mt][nt][0] + b0, acc[mt][nt][1] + b1);
            float2 v1 = make_float2(acc[mt][nt][2] + b0, acc[mt][nt][3] + b1);
            *(float2*)c0 = v0;
            *(float2*)c1 = v1;
        }
    }
}

// ---------------- fp32 -> (bf16 hi, bf16 lo) split ----------------
__global__ void conv_split(const float* __restrict__ src,
                           __nv_bfloat16* __restrict__ hi,
                           __nv_bfloat16* __restrict__ lo, int n4)
{
    for (int i = blockIdx.x * blockDim.x + threadIdx.x; i < n4; i += gridDim.x * blockDim.x) {
        float4 v = ((const float4*)src)[i];
        __nv_bfloat16 h0 = __float2bfloat16(v.x);
        __nv_bfloat16 h1 = __float2bfloat16(v.y);
        __nv_bfloat16 h2 = __float2bfloat16(v.z);
        __nv_bfloat16 h3 = __float2bfloat16(v.w);
        __nv_bfloat16 l0 = __float2bfloat16(v.x - __bfloat162float(h0));
        __nv_bfloat16 l1 = __float2bfloat16(v.y - __bfloat162float(h1));
        __nv_bfloat16 l2 = __float2bfloat16(v.z - __bfloat162float(h2));
        __nv_bfloat16 l3 = __float2bfloat16(v.w - __bfloat162float(h3));
        __nv_bfloat162* hp = (__nv_bfloat162*)hi;
        __nv_bfloat162* lp = (__nv_bfloat162*)lo;
        hp[i * 2]     = __nv_bfloat162(h0, h1);
        hp[i * 2 + 1] = __nv_bfloat162(h2, h3);
        lp[i * 2]     = __nv_bfloat162(l0, l1);
        lp[i * 2 + 1] = __nv_bfloat162(l2, l3);
    }
}

// ---------------- prep: Acat hi/lo (padded [A; router_w]), B2 hi/lo ---------
__global__ void prep2_kernel(const float* __restrict__ A,
                             const float* __restrict__ router_w,
                             const float* __restrict__ B)
{
    const int n1 = 128 * DIN;
    const int n2 = DOUT * K2DIM;
    for (int idx = blockIdx.x * blockDim.x + threadIdx.x; idx < n1 + n2; idx += gridDim.x * blockDim.x) {
        if (idx < n1) {
            int row = idx / DIN, col = idx - row * DIN;
            float v = 0.0f;
            if (row < RNK)             v = A[row * DIN + col];
            else if (row < RNK + NEXP) v = router_w[(row - RNK) * DIN + col];
            __nv_bfloat16 h = __float2bfloat16(v);
            g_AcatHi[idx] = h;
            g_AcatLo[idx] = __float2bfloat16(v - __bfloat162float(h));
        } else {
            int j = idx - n1;
            int o = j / K2DIM;
            int er = j - o * K2DIM;
            int e = er >> 6, r = er & 63;
            float v = SCALING * B[((size_t)e * DOUT + o) * RNK + r];
            __nv_bfloat16 h = __float2bfloat16(v);
            g_B2hi[j] = h;
            g_B2lo[j] = __float2bfloat16(v - __bfloat162float(h));
        }
    }
}

// ---------------- routing: softmax/top-2 -> dense G (hi/lo bf16) -----------
__global__ void route_kernel(int T)
{
    int warp = (blockIdx.x * blockDim.x + threadIdx.x) >> 5;
    int lane = threadIdx.x & 31;
    if (warp >= T) return;

    const float* h = g_H + (size_t)warp * 128;

    float logit = (lane < NEXP) ? h[64 + lane] : -1e30f;
    float m = logit;
    #pragma unroll
    for (int off = 16; off; off >>= 1)
        m = fmaxf(m, __shfl_xor_sync(0xffffffffu, m, off));
    float p = (lane < NEXP) ? expf(logit - m) : 0.0f;
    float s = p;
    #pragma unroll
    for (int off = 16; off; off >>= 1)
        s += __shfl_xor_sync(0xffffffffu, s, off);
    p /= s;

    float v1 = p; int i1 = lane;
    #pragma unroll
    for (int off = 16; off; off >>= 1) {
        float ov = __shfl_xor_sync(0xffffffffu, v1, off);
        int   oi = __shfl_xor_sync(0xffffffffu, i1, off);
        if (ov > v1 || (ov == v1 && oi < i1)) { v1 = ov; i1 = oi; }
    }
    float v2 = (lane == i1) ? -1.0f : p; int i2 = lane;
    #pragma unroll
    for (int off = 16; off; off >>= 1) {
        float ov = __shfl_xor_sync(0xffffffffu, v2, off);
        int   oi = __shfl_xor_sync(0xffffffffu, i2, off);
        if (ov > v2 || (ov == v2 && oi < i2)) { v2 = ov; i2 = oi; }
    }

    float snorm = v1 + v2 + 1e-6f;
    float w0 = v1 / snorm, w1 = v2 / snorm;

    __nv_bfloat16* Gh = g_Ghi + (size_t)warp * K2DIM;
    __nv_bfloat16* Gl = g_Glo + (size_t)warp * K2DIM;
    for (int j = lane; j < K2DIM; j += 32) {
        int e = j >> 6, r = j & 63;
        float val = 0.0f;
        if (e == i1)      val = w0 * h[r];
        else if (e == i2) val = w1 * h[r];
        __nv_bfloat16 hh = __float2bfloat16(val);
        Gh[j] = hh;
        Gl[j] = __float2bfloat16(val - __bfloat162float(hh));
    }
}

// ---------------------------------------------------------------------------
extern "C" void kernel_launch(void* const* d_in, const int* in_sizes, int n_in,
                              void* d_out, int out_size)
{
    const float* x        = (const float*)d_in[0];
    const float* base_w   = (const float*)d_in[1];
    const float* base_b   = (const float*)d_in[2];
    const float* A        = (const float*)d_in[3];
    const float* B        = (const float*)d_in[4];
    const float* router_w = (const float*)d_in[5];
    float* out = (float*)d_out;

    const int T = in_sizes[0] / DIN;    // 8192

    __nv_bfloat16 *dXhi, *dXlo, *dWhi, *dWlo, *dAh, *dAl, *dGh, *dGl, *dB2h, *dB2l;
    float* dH;
    cudaGetSymbolAddress((void**)&dXhi, g_Xhi);
    cudaGetSymbolAddress((void**)&dXlo, g_Xlo);
    cudaGetSymbolAddress((void**)&dWhi, g_Whi);
    cudaGetSymbolAddress((void**)&dWlo, g_Wlo);
    cudaGetSymbolAddress((void**)&dAh,  g_AcatHi);
    cudaGetSymbolAddress((void**)&dAl,  g_AcatLo);
    cudaGetSymbolAddress((void**)&dGh,  g_Ghi);
    cudaGetSymbolAddress((void**)&dGl,  g_Glo);
    cudaGetSymbolAddress((void**)&dB2h, g_B2hi);
    cudaGetSymbolAddress((void**)&dB2l, g_B2lo);
    cudaGetSymbolAddress((void**)&dH,   g_H);

    const int smem = STAGES * 2 * 128 * RSB;   // 3 * 36864 = 110592
    cudaFuncSetAttribute(gemm_hmma, cudaFuncAttributeMaxDynamicSharedMemorySize, smem);

    // 1) split conversions
    conv_split<<<1024, 256>>>(x,      dXhi, dXlo, T * DIN / 4);
    conv_split<<<1024, 256>>>(base_w, dWhi, dWlo, DOUT * DIN / 4);
    prep2_kernel<<<1024, 256>>>(A, router_w, B);

    // 2) H = X @ Acat^T  (3-term split) -> g_H [T,128] fp32
    {
        SegList SL;
        SL.s[0] = { dXhi, dAh, DIN / 64, DIN, DIN };
        SL.s[1] = { dXhi, dAl, DIN / 64, DIN, DIN };
        SL.s[2] = { dXlo, dAh, DIN / 64, DIN, DIN };
        dim3 grid(1, T / 128);
        gemm_hmma<<<grid, 256, smem>>>(SL, 3, nullptr, dH, 128);
    }

    // 3) routing -> dense G (hi/lo)
    route_kernel<<<(T + 7) / 8, 256>>>(T);

    // 4) out = X @ W^T + G @ B2^T + bias  (one fused accumulation)
    {
        SegList SL;
        SL.s[0] = { dXhi, dWhi, DIN / 64,   DIN,   DIN };
        SL.s[1] = { dXhi, dWlo, DIN / 64,   DIN,   DIN };
        SL.s[2] = { dXlo, dWhi, DIN / 64,   DIN,   DIN };
        SL.s[3] = { dGh,  dB2h, K2DIM / 64, K2DIM, K2DIM };
        SL.s[4] = { dGh,  dB2l, K2DIM / 64, K2DIM, K2DIM };
        SL.s[5] = { dGl,  dB2h, K2DIM / 64, K2DIM, K2DIM };
        dim3 grid(DOUT / 128, T / 128);
        gemm_hmma<<<grid, 256, smem>>>(SL, 6, base_b, out, DOUT);
    }
}

// round 12
// speedup vs baseline: 2.8783x; 1.0087x over previous
#include <cuda_runtime.h>
#include <cuda_bf16.h>
#include <math.h>
#include <stdint.h>

// Problem constants
#define DIN   4096
#define DOUT  4096
#define RNK   64
#define NEXP  16
#define K2DIM 1024
#define MAXT  8192
#define SCALING 0.5f

#define RS 72                 // smem row stride in bf16 elems (144 B) -> conflict-free
#define RSB (RS * 2)          // 144 bytes

// ---------------- scratch (device globals) ----------------
__device__ __align__(16) __nv_bfloat16 g_Xhi[MAXT * DIN];
__device__ __align__(16) __nv_bfloat16 g_Xlo[MAXT * DIN];
__device__ __align__(16) __nv_bfloat16 g_Whi[DOUT * DIN];
__device__ __align__(16) __nv_bfloat16 g_Wlo[DOUT * DIN];
__device__ __align__(16) __nv_bfloat16 g_AcatHi[128 * DIN];
__device__ __align__(16) __nv_bfloat16 g_AcatLo[128 * DIN];
__device__ __align__(16) __nv_bfloat16 g_Ghi[MAXT * K2DIM];
__device__ __align__(16) __nv_bfloat16 g_Glo[MAXT * K2DIM];
__device__ __align__(16) __nv_bfloat16 g_B2hi[DOUT * K2DIM];
__device__ __align__(16) __nv_bfloat16 g_B2lo[DOUT * K2DIM];
__device__ __align__(16) float g_H[MAXT * 128];

// ---------------- PTX helpers (baseline ISA only) ----------------
__device__ __forceinline__ uint32_t smem_u32(const void* p) {
    uint32_t a;
    asm("{ .reg .u64 t; cvta.to.shared.u64 t, %1; cvt.u32.u64 %0, t; }" : "=r"(a) : "l"(p));
    return a;
}
__device__ __forceinline__ void cpasync16(uint32_t s, const void* g) {
    asm volatile("cp.async.cg.shared.global [%0], [%1], 16;" :: "r"(s), "l"(g));
}
__device__ __forceinline__ void cp_commit() { asm volatile("cp.async.commit_group;" ::: "memory"); }
template<int N> __device__ __forceinline__ void cp_wait() {
    asm volatile("cp.async.wait_group %0;" :: "n"(N) : "memory");
}
__device__ __forceinline__ void ldsm4(uint32_t& r0, uint32_t& r1, uint32_t& r2, uint32_t& r3, uint32_t a) {
    asm volatile("ldmatrix.sync.aligned.m8n8.x4.shared.b16 {%0,%1,%2,%3}, [%4];"
                 : "=r"(r0), "=r"(r1), "=r"(r2), "=r"(r3) : "r"(a));
}
__device__ __forceinline__ void mma16816(float* c,
                                         uint32_t a0, uint32_t a1, uint32_t a2, uint32_t a3,
                                         uint32_t b0, uint32_t b1) {
    asm volatile("mma.sync.aligned.m16n8k16.row.col.f32.bf16.bf16.f32 "
                 "{%0,%1,%2,%3},{%4,%5,%6,%7},{%8,%9},{%0,%1,%2,%3};"
                 : "+f"(c[0]), "+f"(c[1]), "+f"(c[2]), "+f"(c[3])
                 : "r"(a0), "r"(a1), "r"(a2), "r"(a3), "r"(b0), "r"(b1));
}

// ---------------- segment descriptor ----------------
struct Seg { const __nv_bfloat16* A; const __nv_bfloat16* B; int ktiles; int lda; int ldb; };
struct SegList { Seg s[6]; };

// ============================================================================
// Main GEMM: 128x256 tile, BK=64, 2-stage double buffer, 8 warps (64x64 each)
// C[M,N] = sum_seg Aseg@Bseg^T + bias
// ============================================================================
__global__ void __launch_bounds__(256)
gemm_hmma256(SegList SL, int nseg, const float* __restrict__ bias,
             float* __restrict__ C, int ldc)
{
    extern __shared__ char smem[];
    const uint32_t sb = smem_u32(smem);
    const int tid  = threadIdx.x;
    const int wid  = tid >> 5, lane = tid & 31;
    const int m0   = blockIdx.y * 128;
    const int n0   = blockIdx.x * 256;
    const int wm   = (wid >> 2) * 64;   // 0 / 64
    const int wn   = (wid & 3) * 64;    // 0/64/128/192

    constexpr int ASTAGE = 128 * RSB;        // 18432 B
    constexpr int BSTAGE = 256 * RSB;        // 36864 B
    constexpr int STAGEB = ASTAGE + BSTAGE;  // 55296 B

    float acc[4][8][4];
    #pragma unroll
    for (int i = 0; i < 4; i++)
        #pragma unroll
        for (int j = 0; j < 8; j++)
            #pragma unroll
            for (int q = 0; q < 4; q++) acc[i][j][q] = 0.0f;

    int total = 0;
    #pragma unroll
    for (int i = 0; i < 6; i++) if (i < nseg) total += SL.s[i].ktiles;

    int sg = 0, ktin = 0;
    auto load_stage = [&](int slot) {
        const Seg& S = SL.s[sg];
        const int lda2 = S.lda * 2, ldb2 = S.ldb * 2;
        const char* gA = (const char*)S.A + (size_t)m0 * lda2 + ktin * 128;
        const char* gB = (const char*)S.B + (size_t)n0 * ldb2 + ktin * 128;
        uint32_t sA = sb + slot * STAGEB;
        uint32_t sB = sA + ASTAGE;
        #pragma unroll
        for (int i = 0; i < 4; i++) {          // A: 128 rows x 8 chunks
            int ch = tid + i * 256;
            int row = ch >> 3, cc = ch & 7;
            cpasync16(sA + row * RSB + cc * 16, gA + (size_t)row * lda2 + cc * 16);
        }
        #pragma unroll
        for (int i = 0; i < 8; i++) {          // B: 256 rows x 8 chunks
            int ch = tid + i * 256;
            int row = ch >> 3, cc = ch & 7;
            cpasync16(sB + row * RSB + cc * 16, gB + (size_t)row * ldb2 + cc * 16);
        }
        if (++ktin == S.ktiles) { ktin = 0; sg++; }
    };

    auto compute_stage = [&](int slot) {
        uint32_t sA = sb + slot * STAGEB;
        uint32_t sB = sA + ASTAGE;
        #pragma unroll
        for (int kc = 0; kc < 4; kc++) {
            uint32_t a[4][4];
            #pragma unroll
            for (int mt = 0; mt < 4; mt++) {
                int row = wm + mt * 16 + (lane & 15);
                uint32_t addr = sA + row * RSB + kc * 32 + (lane >> 4) * 16;
                ldsm4(a[mt][0], a[mt][1], a[mt][2], a[mt][3], addr);
            }
            uint32_t b[4][4];
            #pragma unroll
            for (int ng = 0; ng < 4; ng++) {
                int n = wn + ng * 16 + (lane & 7) + ((lane >> 4) << 3);
                uint32_t addr = sB + n * RSB + kc * 32 + ((lane >> 3) & 1) * 16;
                ldsm4(b[ng][0], b[ng][1], b[ng][2], b[ng][3], addr);
            }
            #pragma unroll
            for (int mt = 0; mt < 4; mt++)
                #pragma unroll
                for (int nt = 0; nt < 8; nt++)
                    mma16816(acc[mt][nt],
                             a[mt][0], a[mt][1], a[mt][2], a[mt][3],
                             b[nt >> 1][(nt & 1) * 2], b[nt >> 1][(nt & 1) * 2 + 1]);
        }
    };

    load_stage(0); cp_commit();

    for (int t = 0; t < total; t++) {
        if (t + 1 < total) { load_stage((t + 1) & 1); cp_commit(); cp_wait<1>(); }
        else               { cp_wait<0>(); }
        __syncthreads();
        compute_stage(t & 1);
        __syncthreads();
    }

    // epilogue
    #pragma unroll
    for (int mt = 0; mt < 4; mt++) {
        #pragma unroll
        for (int nt = 0; nt < 8; nt++) {
            int row = m0 + wm + mt * 16 + (lane >> 2);
            int col = n0 + wn + nt * 8 + (lane & 3) * 2;
            float b0 = __ldg(bias + col), b1 = __ldg(bias + col + 1);
            float* c0 = C + (size_t)row * ldc + col;
            float* c1 = C + (size_t)(row + 8) * ldc + col;
            *(float2*)c0 = make_float2(acc[mt][nt][0] + b0, acc[mt][nt][1] + b1);
            *(float2*)c1 = make_float2(acc[mt][nt][2] + b0, acc[mt][nt][3] + b1);
        }
    }
}

// ============================================================================
// H GEMM, split-K: grid.x = seg*2+half; 128x128 tile, 3-stage; atomicAdd epi.
// ============================================================================
__global__ void __launch_bounds__(256)
gemm_hmma_ks(SegList SL, float* __restrict__ C, int ldc)
{
    extern __shared__ char smem[];
    const uint32_t sb = smem_u32(smem);
    const int tid  = threadIdx.x;
    const int wid  = tid >> 5, lane = tid & 31;
    const int m0   = blockIdx.y * 128;
    const int seg  = blockIdx.x >> 1;
    const int half = blockIdx.x & 1;
    const int wm   = (wid >> 2) * 64;
    const int wn   = (wid & 3) * 32;

    constexpr int ASTAGE = 128 * RSB;
    constexpr int STAGEB = 2 * ASTAGE;

    const Seg S = SL.s[seg];
    const int nkt = S.ktiles >> 1;
    const int kt0 = half * nkt;
    const int lda2 = S.lda * 2, ldb2 = S.ldb * 2;

    float acc[4][4][4];
    #pragma unroll
    for (int i = 0; i < 4; i++)
        #pragma unroll
        for (int j = 0; j < 4; j++)
            #pragma unroll
            for (int q = 0; q < 4; q++) acc[i][j][q] = 0.0f;

    auto load_stage = [&](int slot, int kt) {
        const char* gA = (const char*)S.A + (size_t)m0 * lda2 + (kt0 + kt) * 128;
        const char* gB = (const char*)S.B + (kt0 + kt) * 128;
        uint32_t sA = sb + slot * STAGEB;
        uint32_t sB = sA + ASTAGE;
        #pragma unroll
        for (int i = 0; i < 4; i++) {
            int ch = tid + i * 256;
            int row = ch >> 3, cc = ch & 7;
            cpasync16(sA + row * RSB + cc * 16, gA + (size_t)row * lda2 + cc * 16);
            cpasync16(sB + row * RSB + cc * 16, gB + (size_t)row * ldb2 + cc * 16);
        }
    };

    auto compute_stage = [&](int slot) {
        uint32_t sA = sb + slot * STAGEB;
        uint32_t sB = sA + ASTAGE;
        #pragma unroll
        for (int kc = 0; kc < 4; kc++) {
            uint32_t a[4][4];
            #pragma unroll
            for (int mt = 0; mt < 4; mt++) {
                int row = wm + mt * 16 + (lane & 15);
                uint32_t addr = sA + row * RSB + kc * 32 + (lane >> 4) * 16;
                ldsm4(a[mt][0], a[mt][1], a[mt][2], a[mt][3], addr);
            }
            uint32_t b[2][4];
            #pragma unroll
            for (int ng = 0; ng < 2; ng++) {
                int n = wn + ng * 16 + (lane & 7) + ((lane >> 4) << 3);
                uint32_t addr = sB + n * RSB + kc * 32 + ((lane >> 3) & 1) * 16;
                ldsm4(b[ng][0], b[ng][1], b[ng][2], b[ng][3], addr);
            }
            #pragma unroll
            for (int mt = 0; mt < 4; mt++)
                #pragma unroll
                for (int nt = 0; nt < 4; nt++)
                    mma16816(acc[mt][nt],
                             a[mt][0], a[mt][1], a[mt][2], a[mt][3],
                             b[nt >> 1][(nt & 1) * 2], b[nt >> 1][(nt & 1) * 2 + 1]);
        }
    };

    load_stage(0, 0); cp_commit();
    load_stage(1, 1); cp_commit();

    for (int t = 0; t < nkt; t++) {
        cp_wait<1>();
        __syncthreads();
        if (t + 2 < nkt) load_stage((t + 2) % 3, t + 2);
        cp_commit();
        compute_stage(t % 3);
    }

    #pragma unroll
    for (int mt = 0; mt < 4; mt++) {
        #pragma unroll
        for (int nt = 0; nt < 4; nt++) {
            int row = m0 + wm + mt * 16 + (lane >> 2);
            int col = wn + nt * 8 + (lane & 3) * 2;
            float* c0 = C + (size_t)row * ldc + col;
            float* c1 = C + (size_t)(row + 8) * ldc + col;
            atomicAdd(c0,     acc[mt][nt][0]);
            atomicAdd(c0 + 1, acc[mt][nt][1]);
            atomicAdd(c1,     acc[mt][nt][2]);
            atomicAdd(c1 + 1, acc[mt][nt][3]);
        }
    }
}

// ---------------- fp32 -> (bf16 hi, bf16 lo) split ----------------
__global__ void conv_split(const float* __restrict__ src,
                           __nv_bfloat16* __restrict__ hi,
                           __nv_bfloat16* __restrict__ lo, int n4)
{
    for (int i = blockIdx.x * blockDim.x + threadIdx.x; i < n4; i += gridDim.x * blockDim.x) {
        float4 v = ((const float4*)src)[i];
        __nv_bfloat16 h0 = __float2bfloat16(v.x);
        __nv_bfloat16 h1 = __float2bfloat16(v.y);
        __nv_bfloat16 h2 = __float2bfloat16(v.z);
        __nv_bfloat16 h3 = __float2bfloat16(v.w);
        __nv_bfloat16 l0 = __float2bfloat16(v.x - __bfloat162float(h0));
        __nv_bfloat16 l1 = __float2bfloat16(v.y - __bfloat162float(h1));
        __nv_bfloat16 l2 = __float2bfloat16(v.z - __bfloat162float(h2));
        __nv_bfloat16 l3 = __float2bfloat16(v.w - __bfloat162float(h3));
        __nv_bfloat162* hp = (__nv_bfloat162*)hi;
        __nv_bfloat162* lp = (__nv_bfloat162*)lo;
        hp[i * 2]     = __nv_bfloat162(h0, h1);
        hp[i * 2 + 1] = __nv_bfloat162(h2, h3);
        lp[i * 2]     = __nv_bfloat162(l0, l1);
        lp[i * 2 + 1] = __nv_bfloat162(l2, l3);
    }
}

// ---------------- prep: Acat hi/lo, B2 hi/lo ----------------
__global__ void prep2_kernel(const float* __restrict__ A,
                             const float* __restrict__ router_w,
                             const float* __restrict__ B)
{
    const int n1 = 128 * DIN;
    const int n2 = DOUT * K2DIM;
    for (int idx = blockIdx.x * blockDim.x + threadIdx.x; idx < n1 + n2; idx += gridDim.x * blockDim.x) {
        if (idx < n1) {
            int row = idx / DIN, col = idx - row * DIN;
            float v = 0.0f;
            if (row < RNK)             v = A[row * DIN + col];
            else if (row < RNK + NEXP) v = router_w[(row - RNK) * DIN + col];
            __nv_bfloat16 h = __float2bfloat16(v);
            g_AcatHi[idx] = h;
            g_AcatLo[idx] = __float2bfloat16(v - __bfloat162float(h));
        } else {
            int j = idx - n1;
            int o = j / K2DIM;
            int er = j - o * K2DIM;
            int e = er >> 6, r = er & 63;
            float v = SCALING * B[((size_t)e * DOUT + o) * RNK + r];
            __nv_bfloat16 h = __float2bfloat16(v);
            g_B2hi[j] = h;
            g_B2lo[j] = __float2bfloat16(v - __bfloat162float(h));
        }
    }
}

// ---------------- routing ----------------
__global__ void route_kernel(int T)
{
    int warp = (blockIdx.x * blockDim.x + threadIdx.x) >> 5;
    int lane = threadIdx.x & 31;
    if (warp >= T) return;

    const float* h = g_H + (size_t)warp * 128;

    float logit = (lane < NEXP) ? h[64 + lane] : -1e30f;
    float m = logit;
    #pragma unroll
    for (int off = 16; off; off >>= 1)
        m = fmaxf(m, __shfl_xor_sync(0xffffffffu, m, off));
    float p = (lane < NEXP) ? expf(logit - m) : 0.0f;
    float s = p;
    #pragma unroll
    for (int off = 16; off; off >>= 1)
        s += __shfl_xor_sync(0xffffffffu, s, off);
    p /= s;

    float v1 = p; int i1 = lane;
    #pragma unroll
    for (int off = 16; off; off >>= 1) {
        float ov = __shfl_xor_sync(0xffffffffu, v1, off);
        int   oi = __shfl_xor_sync(0xffffffffu, i1, off);
        if (ov > v1 || (ov == v1 && oi < i1)) { v1 = ov; i1 = oi; }
    }
    float v2 = (lane == i1) ? -1.0f : p; int i2 = lane;
    #pragma unroll
    for (int off = 16; off; off >>= 1) {
        float ov = __shfl_xor_sync(0xffffffffu, v2, off);
        int   oi = __shfl_xor_sync(0xffffffffu, i2, off);
        if (ov > v2 || (ov == v2 && oi < i2)) { v2 = ov; i2 = oi; }
    }

    float snorm = v1 + v2 + 1e-6f;
    float w0 = v1 / snorm, w1 = v2 / snorm;

    __nv_bfloat16* Gh = g_Ghi + (size_t)warp * K2DIM;
    __nv_bfloat16* Gl = g_Glo + (size_t)warp * K2DIM;
    for (int j = lane; j < K2DIM; j += 32) {
        int e = j >> 6, r = j & 63;
        float val = 0.0f;
        if (e == i1)      val = w0 * h[r];
        else if (e == i2) val = w1 * h[r];
        __nv_bfloat16 hh = __float2bfloat16(val);
        Gh[j] = hh;
        Gl[j] = __float2bfloat16(val - __bfloat162float(hh));
    }
}

// ---------------------------------------------------------------------------
extern "C" void kernel_launch(void* const* d_in, const int* in_sizes, int n_in,
                              void* d_out, int out_size)
{
    const float* x        = (const float*)d_in[0];
    const float* base_w   = (const float*)d_in[1];
    const float* base_b   = (const float*)d_in[2];
    const float* A        = (const float*)d_in[3];
    const float* B        = (const float*)d_in[4];
    const float* router_w = (const float*)d_in[5];
    float* out = (float*)d_out;

    const int T = in_sizes[0] / DIN;    // 8192

    __nv_bfloat16 *dXhi, *dXlo, *dWhi, *dWlo, *dAh, *dAl, *dGh, *dGl, *dB2h, *dB2l;
    float* dH;
    cudaGetSymbolAddress((void**)&dXhi, g_Xhi);
    cudaGetSymbolAddress((void**)&dXlo, g_Xlo);
    cudaGetSymbolAddress((void**)&dWhi, g_Whi);
    cudaGetSymbolAddress((void**)&dWlo, g_Wlo);
    cudaGetSymbolAddress((void**)&dAh,  g_AcatHi);
    cudaGetSymbolAddress((void**)&dAl,  g_AcatLo);
    cudaGetSymbolAddress((void**)&dGh,  g_Ghi);
    cudaGetSymbolAddress((void**)&dGl,  g_Glo);
    cudaGetSymbolAddress((void**)&dB2h, g_B2hi);
    cudaGetSymbolAddress((void**)&dB2l, g_B2lo);
    cudaGetSymbolAddress((void**)&dH,   g_H);

    const int smem_ks  = 3 * 2 * 128 * RSB;            // 110592
    const int smem_256 = 2 * (128 + 256) * RSB;        // 110592
    cudaFuncSetAttribute(gemm_hmma_ks,  cudaFuncAttributeMaxDynamicSharedMemorySize, smem_ks);
    cudaFuncSetAttribute(gemm_hmma256, cudaFuncAttributeMaxDynamicSharedMemorySize, smem_256);

    // 1) split conversions
    conv_split<<<1024, 256>>>(x,      dXhi, dXlo, T * DIN / 4);
    conv_split<<<1024, 256>>>(base_w, dWhi, dWlo, DOUT * DIN / 4);
    prep2_kernel<<<1024, 256>>>(A, router_w, B);

    // 2) H = X @ Acat^T (3-term split), split-K over (seg, half) -> atomicAdd
    cudaMemsetAsync(dH, 0, (size_t)T * 128 * sizeof(float));
    {
        SegList SL;
        SL.s[0] = { dXhi, dAh, DIN / 64, DIN, DIN };
        SL.s[1] = { dXhi, dAl, DIN / 64, DIN, DIN };
        SL.s[2] = { dXlo, dAh, DIN / 64, DIN, DIN };
        dim3 grid(6, T / 128);
        gemm_hmma_ks<<<grid, 256, smem_ks>>>(SL, dH, 128);
    }

    // 3) routing -> dense G (hi/lo)
    route_kernel<<<(T + 7) / 8, 256>>>(T);

    // 4) out = X @ W^T + G @ B2^T + bias  (128x256 tiles)
    {
        SegList SL;
        SL.s[0] = { dXhi, dWhi, DIN / 64,   DIN,   DIN };
        SL.s[1] = { dXhi, dWlo, DIN / 64,   DIN,   DIN };
        SL.s[2] = { dXlo, dWhi, DIN / 64,   DIN,   DIN };
        SL.s[3] = { dGh,  dB2h, K2DIM / 64, K2DIM, K2DIM };
        SL.s[4] = { dGh,  dB2l, K2DIM / 64, K2DIM, K2DIM };
        SL.s[5] = { dGl,  dB2h, K2DIM / 64, K2DIM, K2DIM };
        dim3 grid(DOUT / 256, T / 128);
        gemm_hmma256<<<grid, 256, smem_256>>>(SL, 6, base_b, out, DOUT);
    }
}

// round 14
// speedup vs baseline: 3.1775x; 1.1039x over previous
#include <cuda_runtime.h>
#include <cuda_bf16.h>
#include <math.h>
#include <stdint.h>

// Problem constants
#define DIN   4096
#define DOUT  4096
#define RNK   64
#define NEXP  16
#define K2DIM 1024
#define MAXT  8192
#define SCALING 0.5f

#define RS 72                 // smem row stride in bf16 elems (144 B) -> conflict-free
#define RSB (RS * 2)          // 144 bytes

// ---------------- scratch (device globals) ----------------
__device__ __align__(16) __nv_bfloat16 g_Xhi[MAXT * DIN];
__device__ __align__(16) __nv_bfloat16 g_Xlo[MAXT * DIN];
__device__ __align__(16) __nv_bfloat16 g_Whi[DOUT * DIN];
__device__ __align__(16) __nv_bfloat16 g_Wlo[DOUT * DIN];
__device__ __align__(16) __nv_bfloat16 g_AcatHi[128 * DIN];
__device__ __align__(16) __nv_bfloat16 g_AcatLo[128 * DIN];
__device__ __align__(16) __nv_bfloat16 g_Ghi[MAXT * K2DIM];
__device__ __align__(16) __nv_bfloat16 g_B2hi[DOUT * K2DIM];
__device__ __align__(16) float g_H[MAXT * 128];

// ---------------- PTX helpers (baseline ISA only) ----------------
__device__ __forceinline__ uint32_t smem_u32(const void* p) {
    uint32_t a;
    asm("{ .reg .u64 t; cvta.to.shared.u64 t, %1; cvt.u32.u64 %0, t; }" : "=r"(a) : "l"(p));
    return a;
}
__device__ __forceinline__ void cpasync16(uint32_t s, const void* g) {
    asm volatile("cp.async.cg.shared.global [%0], [%1], 16;" :: "r"(s), "l"(g));
}
__device__ __forceinline__ void cp_commit() { asm volatile("cp.async.commit_group;" ::: "memory"); }
template<int N> __device__ __forceinline__ void cp_wait() {
    asm volatile("cp.async.wait_group %0;" :: "n"(N) : "memory");
}
__device__ __forceinline__ void ldsm4(uint32_t& r0, uint32_t& r1, uint32_t& r2, uint32_t& r3, uint32_t a) {
    asm volatile("ldmatrix.sync.aligned.m8n8.x4.shared.b16 {%0,%1,%2,%3}, [%4];"
                 : "=r"(r0), "=r"(r1), "=r"(r2), "=r"(r3) : "r"(a));
}
__device__ __forceinline__ void mma16816(float* c,
                                         uint32_t a0, uint32_t a1, uint32_t a2, uint32_t a3,
                                         uint32_t b0, uint32_t b1) {
    asm volatile("mma.sync.aligned.m16n8k16.row.col.f32.bf16.bf16.f32 "
                 "{%0,%1,%2,%3},{%4,%5,%6,%7},{%8,%9},{%0,%1,%2,%3};"
                 : "+f"(c[0]), "+f"(c[1]), "+f"(c[2]), "+f"(c[3])
                 : "r"(a0), "r"(a1), "r"(a2), "r"(a3), "r"(b0), "r"(b1));
}

// ---------------- segment descriptor ----------------
struct Seg { const __nv_bfloat16* A; const __nv_bfloat16* B; int ktiles; int lda; int ldb; };
struct SegList { Seg s[6]; };

// ============================================================================
// Main GEMM: 128x256 tile, BK=64, 3-stage ring (one sync/iter), 8 warps
// (64x64 each), fragment double-buffering across k16 chunks.
// C[M,N] = sum_seg Aseg@Bseg^T + bias
// ============================================================================
__global__ void __launch_bounds__(256)
gemm_hmma256(SegList SL, int nseg, const float* __restrict__ bias,
             float* __restrict__ C, int ldc)
{
    extern __shared__ char smem[];
    const uint32_t sb = smem_u32(smem);
    const int tid  = threadIdx.x;
    const int wid  = tid >> 5, lane = tid & 31;
    const int m0   = blockIdx.y * 128;
    const int n0   = blockIdx.x * 256;
    const int wm   = (wid >> 2) * 64;   // 0 / 64
    const int wn   = (wid & 3) * 64;    // 0/64/128/192

    constexpr int ASTAGE = 128 * RSB;        // 18432 B
    constexpr int BSTAGE = 256 * RSB;        // 36864 B
    constexpr int STAGEB = ASTAGE + BSTAGE;  // 55296 B

    // per-warp fragment base addresses (lane-dependent, kc-invariant parts)
    const uint32_t a_lrow = (lane & 15);
    const uint32_t a_lcol = (lane >> 4) * 16;
    const uint32_t b_lrow = (lane & 7) + ((lane >> 4) << 3);
    const uint32_t b_lcol = ((lane >> 3) & 1) * 16;

    float acc[4][8][4];
    #pragma unroll
    for (int i = 0; i < 4; i++)
        #pragma unroll
        for (int j = 0; j < 8; j++)
            #pragma unroll
            for (int q = 0; q < 4; q++) acc[i][j][q] = 0.0f;

    int total = 0;
    #pragma unroll
    for (int i = 0; i < 6; i++) if (i < nseg) total += SL.s[i].ktiles;

    int sg = 0, ktin = 0;
    auto load_stage = [&](int slot) {
        const Seg& S = SL.s[sg];
        const int lda2 = S.lda * 2, ldb2 = S.ldb * 2;
        const char* gA = (const char*)S.A + (size_t)m0 * lda2 + ktin * 128;
        const char* gB = (const char*)S.B + (size_t)n0 * ldb2 + ktin * 128;
        uint32_t sA = sb + slot * STAGEB;
        uint32_t sB = sA + ASTAGE;
        #pragma unroll
        for (int i = 0; i < 4; i++) {          // A: 128 rows x 8 chunks
            int ch = tid + i * 256;
            int row = ch >> 3, cc = ch & 7;
            cpasync16(sA + row * RSB + cc * 16, gA + (size_t)row * lda2 + cc * 16);
        }
        #pragma unroll
        for (int i = 0; i < 8; i++) {          // B: 256 rows x 8 chunks
            int ch = tid + i * 256;
            int row = ch >> 3, cc = ch & 7;
            cpasync16(sB + row * RSB + cc * 16, gB + (size_t)row * ldb2 + cc * 16);
        }
        if (++ktin == S.ktiles) { ktin = 0; sg++; }
    };

    auto compute_stage = [&](int slot) {
        uint32_t sA = sb + slot * STAGEB;
        uint32_t sB = sA + ASTAGE;

        uint32_t a[2][4][4], b[2][4][4];
        // prologue: fragments for kc=0
        #pragma unroll
        for (int mt = 0; mt < 4; mt++) {
            uint32_t addr = sA + (wm + mt * 16 + a_lrow) * RSB + a_lcol;
            ldsm4(a[0][mt][0], a[0][mt][1], a[0][mt][2], a[0][mt][3], addr);
        }
        #pragma unroll
        for (int ng = 0; ng < 4; ng++) {
            uint32_t addr = sB + (wn + ng * 16 + b_lrow) * RSB + b_lcol;
            ldsm4(b[0][ng][0], b[0][ng][1], b[0][ng][2], b[0][ng][3], addr);
        }
        #pragma unroll
        for (int kc = 0; kc < 4; kc++) {
            const int cur = kc & 1, nxt = cur ^ 1;
            if (kc < 3) {
                #pragma unroll
                for (int mt = 0; mt < 4; mt++) {
                    uint32_t addr = sA + (wm + mt * 16 + a_lrow) * RSB + (kc + 1) * 32 + a_lcol;
                    ldsm4(a[nxt][mt][0], a[nxt][mt][1], a[nxt][mt][2], a[nxt][mt][3], addr);
                }
                #pragma unroll
                for (int ng = 0; ng < 4; ng++) {
                    uint32_t addr = sB + (wn + ng * 16 + b_lrow) * RSB + (kc + 1) * 32 + b_lcol;
                    ldsm4(b[nxt][ng][0], b[nxt][ng][1], b[nxt][ng][2], b[nxt][ng][3], addr);
                }
            }
            #pragma unroll
            for (int mt = 0; mt < 4; mt++)
                #pragma unroll
                for (int nt = 0; nt < 8; nt++)
                    mma16816(acc[mt][nt],
                             a[cur][mt][0], a[cur][mt][1], a[cur][mt][2], a[cur][mt][3],
                             b[cur][nt >> 1][(nt & 1) * 2], b[cur][nt >> 1][(nt & 1) * 2 + 1]);
        }
    };

    // prologue: fill stages 0..1
    load_stage(0); cp_commit();
    load_stage(1); cp_commit();

    for (int t = 0; t < total; t++) {
        cp_wait<1>();
        __syncthreads();
        if (t + 2 < total) load_stage((t + 2) % 3);
        cp_commit();
        compute_stage(t % 3);
    }

    // epilogue
    #pragma unroll
    for (int mt = 0; mt < 4; mt++) {
        #pragma unroll
        for (int nt = 0; nt < 8; nt++) {
            int row = m0 + wm + mt * 16 + (lane >> 2);
            int col = n0 + wn + nt * 8 + (lane & 3) * 2;
            float b0 = __ldg(bias + col), b1 = __ldg(bias + col + 1);
            float* c0 = C + (size_t)row * ldc + col;
            float* c1 = C + (size_t)(row + 8) * ldc + col;
            *(float2*)c0 = make_float2(acc[mt][nt][0] + b0, acc[mt][nt][1] + b1);
            *(float2*)c1 = make_float2(acc[mt][nt][2] + b0, acc[mt][nt][3] + b1);
        }
    }
}

// ============================================================================
// H GEMM, split-K: grid.x = seg*2+half; 128x128 tile, 3-stage; atomicAdd epi.
// (unchanged — measured 90 us in R12)
// ============================================================================
__global__ void __launch_bounds__(256)
gemm_hmma_ks(SegList SL, float* __restrict__ C, int ldc)
{
    extern __shared__ char smem[];
    const uint32_t sb = smem_u32(smem);
    const int tid  = threadIdx.x;
    const int wid  = tid >> 5, lane = tid & 31;
    const int m0   = blockIdx.y * 128;
    const int seg  = blockIdx.x >> 1;
    const int half = blockIdx.x & 1;
    const int wm   = (wid >> 2) * 64;
    const int wn   = (wid & 3) * 32;

    constexpr int ASTAGE = 128 * RSB;
    constexpr int STAGEB = 2 * ASTAGE;

    const Seg S = SL.s[seg];
    const int nkt = S.ktiles >> 1;
    const int kt0 = half * nkt;
    const int lda2 = S.lda * 2, ldb2 = S.ldb * 2;

    float acc[4][4][4];
    #pragma unroll
    for (int i = 0; i < 4; i++)
        #pragma unroll
        for (int j = 0; j < 4; j++)
            #pragma unroll
            for (int q = 0; q < 4; q++) acc[i][j][q] = 0.0f;

    auto load_stage = [&](int slot, int kt) {
        const char* gA = (const char*)S.A + (size_t)m0 * lda2 + (kt0 + kt) * 128;
        const char* gB = (const char*)S.B + (kt0 + kt) * 128;
        uint32_t sA = sb + slot * STAGEB;
        uint32_t sB = sA + ASTAGE;
        #pragma unroll
        for (int i = 0; i < 4; i++) {
            int ch = tid + i * 256;
            int row = ch >> 3, cc = ch & 7;
            cpasync16(sA + row * RSB + cc * 16, gA + (size_t)row * lda2 + cc * 16);
            cpasync16(sB + row * RSB + cc * 16, gB + (size_t)row * ldb2 + cc * 16);
        }
    };

    auto compute_stage = [&](int slot) {
        uint32_t sA = sb + slot * STAGEB;
        uint32_t sB = sA + ASTAGE;
        #pragma unroll
        for (int kc = 0; kc < 4; kc++) {
            uint32_t a[4][4];
            #pragma unroll
            for (int mt = 0; mt < 4; mt++) {
                int row = wm + mt * 16 + (lane & 15);
                uint32_t addr = sA + row * RSB + kc * 32 + (lane >> 4) * 16;
                ldsm4(a[mt][0], a[mt][1], a[mt][2], a[mt][3], addr);
            }
            uint32_t b[2][4];
            #pragma unroll
            for (int ng = 0; ng < 2; ng++) {
                int n = wn + ng * 16 + (lane & 7) + ((lane >> 4) << 3);
                uint32_t addr = sB + n * RSB + kc * 32 + ((lane >> 3) & 1) * 16;
                ldsm4(b[ng][0], b[ng][1], b[ng][2], b[ng][3], addr);
            }
            #pragma unroll
            for (int mt = 0; mt < 4; mt++)
                #pragma unroll
                for (int nt = 0; nt < 4; nt++)
                    mma16816(acc[mt][nt],
                             a[mt][0], a[mt][1], a[mt][2], a[mt][3],
                             b[nt >> 1][(nt & 1) * 2], b[nt >> 1][(nt & 1) * 2 + 1]);
        }
    };

    load_stage(0, 0); cp_commit();
    load_stage(1, 1); cp_commit();

    for (int t = 0; t < nkt; t++) {
        cp_wait<1>();
        __syncthreads();
        if (t + 2 < nkt) load_stage((t + 2) % 3, t + 2);
        cp_commit();
        compute_stage(t % 3);
    }

    #pragma unroll
    for (int mt = 0; mt < 4; mt++) {
        #pragma unroll
        for (int nt = 0; nt < 4; nt++) {
            int row = m0 + wm + mt * 16 + (lane >> 2);
            int col = wn + nt * 8 + (lane & 3) * 2;
            float* c0 = C + (size_t)row * ldc + col;
            float* c1 = C + (size_t)(row + 8) * ldc + col;
            atomicAdd(c0,     acc[mt][nt][0]);
            atomicAdd(c0 + 1, acc[mt][nt][1]);
            atomicAdd(c1,     acc[mt][nt][2]);
            atomicAdd(c1 + 1, acc[mt][nt][3]);
        }
    }
}

// ---------------- fp32 -> (bf16 hi, bf16 lo) split ----------------
__global__ void conv_split(const float* __restrict__ src,
                           __nv_bfloat16* __restrict__ hi,
                           __nv_bfloat16* __restrict__ lo, int n4)
{
    for (int i = blockIdx.x * blockDim.x + threadIdx.x; i < n4; i += gridDim.x * blockDim.x) {
        float4 v = ((const float4*)src)[i];
        __nv_bfloat16 h0 = __float2bfloat16(v.x);
        __nv_bfloat16 h1 = __float2bfloat16(v.y);
        __nv_bfloat16 h2 = __float2bfloat16(v.z);
        __nv_bfloat16 h3 = __float2bfloat16(v.w);
        __nv_bfloat16 l0 = __float2bfloat16(v.x - __bfloat162float(h0));
        __nv_bfloat16 l1 = __float2bfloat16(v.y - __bfloat162float(h1));
        __nv_bfloat16 l2 = __float2bfloat16(v.z - __bfloat162float(h2));
        __nv_bfloat16 l3 = __float2bfloat16(v.w - __bfloat162float(h3));
        __nv_bfloat162* hp = (__nv_bfloat162*)hi;
        __nv_bfloat162* lp = (__nv_bfloat162*)lo;
        hp[i * 2]     = __nv_bfloat162(h0, h1);
        hp[i * 2 + 1] = __nv_bfloat162(h2, h3);
        lp[i * 2]     = __nv_bfloat162(l0, l1);
        lp[i * 2 + 1] = __nv_bfloat162(l2, l3);
    }
}

// ---------------- prep: Acat hi/lo, B2 hi (bf16) ----------------
__global__ void prep2_kernel(const float* __restrict__ A,
                             const float* __restrict__ router_w,
                             const float* __restrict__ B)
{
    const int n1 = 128 * DIN;
    const int n2 = DOUT * K2DIM;
    for (int idx = blockIdx.x * blockDim.x + threadIdx.x; idx < n1 + n2; idx += gridDim.x * blockDim.x) {
        if (idx < n1) {
            int row = idx / DIN, col = idx - row * DIN;
            float v = 0.0f;
            if (row < RNK)             v = A[row * DIN + col];
            else if (row < RNK + NEXP) v = router_w[(row - RNK) * DIN + col];
            __nv_bfloat16 h = __float2bfloat16(v);
            g_AcatHi[idx] = h;
            g_AcatLo[idx] = __float2bfloat16(v - __bfloat162float(h));
        } else {
            int j = idx - n1;
            int o = j / K2DIM;
            int er = j - o * K2DIM;
            int e = er >> 6, r = er & 63;
            float v = SCALING * B[((size_t)e * DOUT + o) * RNK + r];
            g_B2hi[j] = __float2bfloat16(v);
        }
    }
}

// ---------------- routing: softmax/top-2 -> dense G (hi bf16 only) ---------
__global__ void route_kernel(int T)
{
    int warp = (blockIdx.x * blockDim.x + threadIdx.x) >> 5;
    int lane = threadIdx.x & 31;
    if (warp >= T) return;

    const float* h = g_H + (size_t)warp * 128;

    float logit = (lane < NEXP) ? h[64 + lane] : -1e30f;
    float m = logit;
    #pragma unroll
    for (int off = 16; off; off >>= 1)
        m = fmaxf(m, __shfl_xor_sync(0xffffffffu, m, off));
    float p = (lane < NEXP) ? expf(logit - m) : 0.0f;
    float s = p;
    #pragma unroll
    for (int off = 16; off; off >>= 1)
        s += __shfl_xor_sync(0xffffffffu, s, off);
    p /= s;

    float v1 = p; int i1 = lane;
    #pragma unroll
    for (int off = 16; off; off >>= 1) {
        float ov = __shfl_xor_sync(0xffffffffu, v1, off);
        int   oi = __shfl_xor_sync(0xffffffffu, i1, off);
        if (ov > v1 || (ov == v1 && oi < i1)) { v1 = ov; i1 = oi; }
    }
    float v2 = (lane == i1) ? -1.0f : p; int i2 = lane;
    #pragma unroll
    for (int off = 16; off; off >>= 1) {
        float ov = __shfl_xor_sync(0xffffffffu, v2, off);
        int   oi = __shfl_xor_sync(0xffffffffu, i2, off);
        if (ov > v2 || (ov == v2 && oi < i2)) { v2 = ov; i2 = oi; }
    }

    float snorm = v1 + v2 + 1e-6f;
    float w0 = v1 / snorm, w1 = v2 / snorm;

    __nv_bfloat16* Gh = g_Ghi + (size_t)warp * K2DIM;
    for (int j = lane; j < K2DIM; j += 32) {
        int e = j >> 6, r = j & 63;
        float val = 0.0f;
        if (e == i1)      val = w0 * h[r];
        else if (e == i2) val = w1 * h[r];
        Gh[j] = __float2bfloat16(val);
    }
}

// ---------------------------------------------------------------------------
extern "C" void kernel_launch(void* const* d_in, const int* in_sizes, int n_in,
                              void* d_out, int out_size)
{
    const float* x        = (const float*)d_in[0];
    const float* base_w   = (const float*)d_in[1];
    const float* base_b   = (const float*)d_in[2];
    const float* A        = (const float*)d_in[3];
    const float* B        = (const float*)d_in[4];
    const float* router_w = (const float*)d_in[5];
    float* out = (float*)d_out;

    const int T = in_sizes[0] / DIN;    // 8192

    __nv_bfloat16 *dXhi, *dXlo, *dWhi, *dWlo, *dAh, *dAl, *dGh, *dB2h;
    float* dH;
    cudaGetSymbolAddress((void**)&dXhi, g_Xhi);
    cudaGetSymbolAddress((void**)&dXlo, g_Xlo);
    cudaGetSymbolAddress((void**)&dWhi, g_Whi);
    cudaGetSymbolAddress((void**)&dWlo, g_Wlo);
    cudaGetSymbolAddress((void**)&dAh,  g_AcatHi);
    cudaGetSymbolAddress((void**)&dAl,  g_AcatLo);
    cudaGetSymbolAddress((void**)&dGh,  g_Ghi);
    cudaGetSymbolAddress((void**)&dB2h, g_B2hi);
    cudaGetSymbolAddress((void**)&dH,   g_H);

    const int smem_ks  = 3 * 2 * 128 * RSB;            // 110592
    const int smem_256 = 3 * (128 + 256) * RSB;        // 165888
    cudaFuncSetAttribute(gemm_hmma_ks,  cudaFuncAttributeMaxDynamicSharedMemorySize, smem_ks);
    cudaFuncSetAttribute(gemm_hmma256, cudaFuncAttributeMaxDynamicSharedMemorySize, smem_256);

    // 1) split conversions
    conv_split<<<1024, 256>>>(x,      dXhi, dXlo, T * DIN / 4);
    conv_split<<<1024, 256>>>(base_w, dWhi, dWlo, DOUT * DIN / 4);
    prep2_kernel<<<1024, 256>>>(A, router_w, B);

    // 2) H = X @ Acat^T (3-term split), split-K over (seg, half) -> atomicAdd
    cudaMemsetAsync(dH, 0, (size_t)T * 128 * sizeof(float));
    {
        SegList SL;
        SL.s[0] = { dXhi, dAh, DIN / 64, DIN, DIN };
        SL.s[1] = { dXhi, dAl, DIN / 64, DIN, DIN };
        SL.s[2] = { dXlo, dAh, DIN / 64, DIN, DIN };
        dim3 grid(6, T / 128);
        gemm_hmma_ks<<<grid, 256, smem_ks>>>(SL, dH, 128);
    }

    // 3) routing -> dense G (hi only; lo correction dropped, err ~1e-4)
    route_kernel<<<(T + 7) / 8, 256>>>(T);

    // 4) out = X @ W^T + G @ B2^T + bias  (4 segments, 128x256 tiles)
    {
        SegList SL;
        SL.s[0] = { dXhi, dWhi, DIN / 64,   DIN,   DIN };
        SL.s[1] = { dXhi, dWlo, DIN / 64,   DIN,   DIN };
        SL.s[2] = { dXlo, dWhi, DIN / 64,   DIN,   DIN };
        SL.s[3] = { dGh,  dB2h, K2DIM / 64, K2DIM, K2DIM };
        dim3 grid(DOUT / 256, T / 128);
        gemm_hmma256<<<grid, 256, smem_256>>>(SL, 4, base_b, out, DOUT);
    }
}

// round 16
// speedup vs baseline: 4.8324x; 1.5208x over previous
#include <cuda_runtime.h>
#include <cuda_fp16.h>
#include <math.h>
#include <stdint.h>

// Problem constants
#define DIN   4096
#define DOUT  4096
#define RNK   64
#define NEXP  16
#define K2DIM 1024
#define MAXT  8192
#define SCALING 0.5f

#define RS 72                 // smem row stride in fp16 elems (144 B) -> conflict-free
#define RSB (RS * 2)          // 144 bytes

// ---------------- scratch (device globals) ----------------
__device__ __align__(16) __half g_Xh[MAXT * DIN];
__device__ __align__(16) __half g_Wh[DOUT * DIN];
__device__ __align__(16) __half g_Wl[DOUT * DIN];
__device__ __align__(16) __half g_Ah[128 * DIN];
__device__ __align__(16) __half g_Al[128 * DIN];
__device__ __align__(16) __half g_Gh[MAXT * K2DIM];
__device__ __align__(16) __half g_B2h[DOUT * K2DIM];
__device__ __align__(16) float g_H[MAXT * 128];

// ---------------- PTX helpers (baseline ISA only) ----------------
__device__ __forceinline__ uint32_t smem_u32(const void* p) {
    uint32_t a;
    asm("{ .reg .u64 t; cvta.to.shared.u64 t, %1; cvt.u32.u64 %0, t; }" : "=r"(a) : "l"(p));
    return a;
}
__device__ __forceinline__ void cpasync16(uint32_t s, const void* g) {
    asm volatile("cp.async.cg.shared.global [%0], [%1], 16;" :: "r"(s), "l"(g));
}
__device__ __forceinline__ void cp_commit() { asm volatile("cp.async.commit_group;" ::: "memory"); }
template<int N> __device__ __forceinline__ void cp_wait() {
    asm volatile("cp.async.wait_group %0;" :: "n"(N) : "memory");
}
__device__ __forceinline__ void ldsm4(uint32_t& r0, uint32_t& r1, uint32_t& r2, uint32_t& r3, uint32_t a) {
    asm volatile("ldmatrix.sync.aligned.m8n8.x4.shared.b16 {%0,%1,%2,%3}, [%4];"
                 : "=r"(r0), "=r"(r1), "=r"(r2), "=r"(r3) : "r"(a));
}
__device__ __forceinline__ void mma16816(float* c,
                                         uint32_t a0, uint32_t a1, uint32_t a2, uint32_t a3,
                                         uint32_t b0, uint32_t b1) {
    asm volatile("mma.sync.aligned.m16n8k16.row.col.f32.f16.f16.f32 "
                 "{%0,%1,%2,%3},{%4,%5,%6,%7},{%8,%9},{%0,%1,%2,%3};"
                 : "+f"(c[0]), "+f"(c[1]), "+f"(c[2]), "+f"(c[3])
                 : "r"(a0), "r"(a1), "r"(a2), "r"(a3), "r"(b0), "r"(b1));
}

// ---------------- segment descriptor ----------------
struct Seg { const __half* A; const __half* B; int ktiles; int lda; int ldb; };
struct SegList { Seg s[4]; };

// ============================================================================
// Main GEMM: 128x128 tile, BK=64, 3-stage ring, 8 warps (64x32), 2 CTAs/SM.
// C[M,N] = sum_seg Aseg@Bseg^T + bias   (R9-proven structure, fp16 operands)
// ============================================================================
__global__ void __launch_bounds__(256, 2)
gemm_hmma(SegList SL, int nseg, const float* __restrict__ bias,
          float* __restrict__ C, int ldc)
{
    extern __shared__ char smem[];
    const uint32_t sb = smem_u32(smem);
    const int tid  = threadIdx.x;
    const int wid  = tid >> 5, lane = tid & 31;
    const int m0   = blockIdx.y * 128;
    const int n0   = blockIdx.x * 128;
    const int wm   = (wid >> 2) * 64;
    const int wn   = (wid & 3) * 32;

    constexpr int ASTAGE = 128 * RSB;
    constexpr int STAGEB = 2 * ASTAGE;

    float acc[4][4][4];
    #pragma unroll
    for (int i = 0; i < 4; i++)
        #pragma unroll
        for (int j = 0; j < 4; j++)
            #pragma unroll
            for (int q = 0; q < 4; q++) acc[i][j][q] = 0.0f;

    int total = 0;
    #pragma unroll
    for (int i = 0; i < 4; i++) if (i < nseg) total += SL.s[i].ktiles;

    int sg = 0, ktin = 0;
    auto load_stage = [&](int slot) {
        const Seg& S = SL.s[sg];
        const int lda2 = S.lda * 2, ldb2 = S.ldb * 2;
        const char* gA = (const char*)S.A + (size_t)m0 * lda2 + ktin * 128;
        const char* gB = (const char*)S.B + (size_t)n0 * ldb2 + ktin * 128;
        uint32_t sA = sb + slot * STAGEB;
        uint32_t sB = sA + ASTAGE;
        #pragma unroll
        for (int i = 0; i < 4; i++) {
            int ch = tid + i * 256;
            int row = ch >> 3, cc = ch & 7;
            cpasync16(sA + row * RSB + cc * 16, gA + (size_t)row * lda2 + cc * 16);
            cpasync16(sB + row * RSB + cc * 16, gB + (size_t)row * ldb2 + cc * 16);
        }
        if (++ktin == S.ktiles) { ktin = 0; sg++; }
    };

    auto compute_stage = [&](int slot) {
        uint32_t sA = sb + slot * STAGEB;
        uint32_t sB = sA + ASTAGE;
        #pragma unroll
        for (int kc = 0; kc < 4; kc++) {
            uint32_t a[4][4];
            #pragma unroll
            for (int mt = 0; mt < 4; mt++) {
                int row = wm + mt * 16 + (lane & 15);
                uint32_t addr = sA + row * RSB + kc * 32 + (lane >> 4) * 16;
                ldsm4(a[mt][0], a[mt][1], a[mt][2], a[mt][3], addr);
            }
            uint32_t b[2][4];
            #pragma unroll
            for (int ng = 0; ng < 2; ng++) {
                int n = wn + ng * 16 + (lane & 7) + ((lane >> 4) << 3);
                uint32_t addr = sB + n * RSB + kc * 32 + ((lane >> 3) & 1) * 16;
                ldsm4(b[ng][0], b[ng][1], b[ng][2], b[ng][3], addr);
            }
            #pragma unroll
            for (int mt = 0; mt < 4; mt++)
                #pragma unroll
                for (int nt = 0; nt < 4; nt++)
                    mma16816(acc[mt][nt],
                             a[mt][0], a[mt][1], a[mt][2], a[mt][3],
                             b[nt >> 1][(nt & 1) * 2], b[nt >> 1][(nt & 1) * 2 + 1]);
        }
    };

    load_stage(0); cp_commit();
    load_stage(1); cp_commit();

    for (int t = 0; t < total; t++) {
        cp_wait<1>();
        __syncthreads();
        if (t + 2 < total) load_stage((t + 2) % 3);
        cp_commit();
        compute_stage(t % 3);
    }

    #pragma unroll
    for (int mt = 0; mt < 4; mt++) {
        #pragma unroll
        for (int nt = 0; nt < 4; nt++) {
            int row = m0 + wm + mt * 16 + (lane >> 2);
            int col = n0 + wn + nt * 8 + (lane & 3) * 2;
            float b0 = __ldg(bias + col), b1 = __ldg(bias + col + 1);
            float* c0 = C + (size_t)row * ldc + col;
            float* c1 = C + (size_t)(row + 8) * ldc + col;
            *(float2*)c0 = make_float2(acc[mt][nt][0] + b0, acc[mt][nt][1] + b1);
            *(float2*)c1 = make_float2(acc[mt][nt][2] + b0, acc[mt][nt][3] + b1);
        }
    }
}

// ============================================================================
// H GEMM, split-K: grid.x = seg*2+half; 128x128 tile, 3-stage; atomicAdd epi.
// ============================================================================
__global__ void __launch_bounds__(256, 2)
gemm_hmma_ks(SegList SL, float* __restrict__ C, int ldc)
{
    extern __shared__ char smem[];
    const uint32_t sb = smem_u32(smem);
    const int tid  = threadIdx.x;
    const int wid  = tid >> 5, lane = tid & 31;
    const int m0   = blockIdx.y * 128;
    const int seg  = blockIdx.x >> 1;
    const int half = blockIdx.x & 1;
    const int wm   = (wid >> 2) * 64;
    const int wn   = (wid & 3) * 32;

    constexpr int ASTAGE = 128 * RSB;
    constexpr int STAGEB = 2 * ASTAGE;

    const Seg S = SL.s[seg];
    const int nkt = S.ktiles >> 1;
    const int kt0 = half * nkt;
    const int lda2 = S.lda * 2, ldb2 = S.ldb * 2;

    float acc[4][4][4];
    #pragma unroll
    for (int i = 0; i < 4; i++)
        #pragma unroll
        for (int j = 0; j < 4; j++)
            #pragma unroll
            for (int q = 0; q < 4; q++) acc[i][j][q] = 0.0f;

    auto load_stage = [&](int slot, int kt) {
        const char* gA = (const char*)S.A + (size_t)m0 * lda2 + (kt0 + kt) * 128;
        const char* gB = (const char*)S.B + (kt0 + kt) * 128;
        uint32_t sA = sb + slot * STAGEB;
        uint32_t sB = sA + ASTAGE;
        #pragma unroll
        for (int i = 0; i < 4; i++) {
            int ch = tid + i * 256;
            int row = ch >> 3, cc = ch & 7;
            cpasync16(sA + row * RSB + cc * 16, gA + (size_t)row * lda2 + cc * 16);
            cpasync16(sB + row * RSB + cc * 16, gB + (size_t)row * ldb2 + cc * 16);
        }
    };

    auto compute_stage = [&](int slot) {
        uint32_t sA = sb + slot * STAGEB;
        uint32_t sB = sA + ASTAGE;
        #pragma unroll
        for (int kc = 0; kc < 4; kc++) {
            uint32_t a[4][4];
            #pragma unroll
            for (int mt = 0; mt < 4; mt++) {
                int row = wm + mt * 16 + (lane & 15);
                uint32_t addr = sA + row * RSB + kc * 32 + (lane >> 4) * 16;
                ldsm4(a[mt][0], a[mt][1], a[mt][2], a[mt][3], addr);
            }
            uint32_t b[2][4];
            #pragma unroll
            for (int ng = 0; ng < 2; ng++) {
                int n = wn + ng * 16 + (lane & 7) + ((lane >> 4) << 3);
                uint32_t addr = sB + n * RSB + kc * 32 + ((lane >> 3) & 1) * 16;
                ldsm4(b[ng][0], b[ng][1], b[ng][2], b[ng][3], addr);
            }
            #pragma unroll
            for (int mt = 0; mt < 4; mt++)
                #pragma unroll
                for (int nt = 0; nt < 4; nt++)
                    mma16816(acc[mt][nt],
                             a[mt][0], a[mt][1], a[mt][2], a[mt][3],
                             b[nt >> 1][(nt & 1) * 2], b[nt >> 1][(nt & 1) * 2 + 1]);
        }
    };

    load_stage(0, 0); cp_commit();
    load_stage(1, 1); cp_commit();

    for (int t = 0; t < nkt; t++) {
        cp_wait<1>();
        __syncthreads();
        if (t + 2 < nkt) load_stage((t + 2) % 3, t + 2);
        cp_commit();
        compute_stage(t % 3);
    }

    #pragma unroll
    for (int mt = 0; mt < 4; mt++) {
        #pragma unroll
        for (int nt = 0; nt < 4; nt++) {
            int row = m0 + wm + mt * 16 + (lane >> 2);
            int col = wn + nt * 8 + (lane & 3) * 2;
            float* c0 = C + (size_t)row * ldc + col;
            float* c1 = C + (size_t)(row + 8) * ldc + col;
            atomicAdd(c0,     acc[mt][nt][0]);
            atomicAdd(c0 + 1, acc[mt][nt][1]);
            atomicAdd(c1,     acc[mt][nt][2]);
            atomicAdd(c1 + 1, acc[mt][nt][3]);
        }
    }
}

// ---------------- fp32 -> fp16 hi (X path: no lo needed) ----------------
__global__ void conv_hi(const float* __restrict__ src, __half* __restrict__ hi, int n4)
{
    for (int i = blockIdx.x * blockDim.x + threadIdx.x; i < n4; i += gridDim.x * blockDim.x) {
        float4 v = ((const float4*)src)[i];
        __half2* hp = (__half2*)hi;
        hp[i * 2]     = __floats2half2_rn(v.x, v.y);
        hp[i * 2 + 1] = __floats2half2_rn(v.z, v.w);
    }
}

// ---------------- fp32 -> (fp16 hi, fp16 lo) split (W path) ----------------
__global__ void conv_hl(const float* __restrict__ src,
                        __half* __restrict__ hi, __half* __restrict__ lo, int n4)
{
    for (int i = blockIdx.x * blockDim.x + threadIdx.x; i < n4; i += gridDim.x * blockDim.x) {
        float4 v = ((const float4*)src)[i];
        __half h0 = __float2half_rn(v.x), h1 = __float2half_rn(v.y);
        __half h2 = __float2half_rn(v.z), h3 = __float2half_rn(v.w);
        __half l0 = __float2half_rn(v.x - __half2float(h0));
        __half l1 = __float2half_rn(v.y - __half2float(h1));
        __half l2 = __float2half_rn(v.z - __half2float(h2));
        __half l3 = __float2half_rn(v.w - __half2float(h3));
        __half2* hp = (__half2*)hi;
        __half2* lp = (__half2*)lo;
        hp[i * 2]     = __halves2half2(h0, h1);
        hp[i * 2 + 1] = __halves2half2(h2, h3);
        lp[i * 2]     = __halves2half2(l0, l1);
        lp[i * 2 + 1] = __halves2half2(l2, l3);
    }
}

// ---------------- prep: Acat hi/lo (fp16), B2 hi (fp16) ----------------
__global__ void prep2_kernel(const float* __restrict__ A,
                             const float* __restrict__ router_w,
                             const float* __restrict__ B)
{
    const int n1 = 128 * DIN;
    const int n2 = DOUT * K2DIM;
    for (int idx = blockIdx.x * blockDim.x + threadIdx.x; idx < n1 + n2; idx += gridDim.x * blockDim.x) {
        if (idx < n1) {
            int row = idx / DIN, col = idx - row * DIN;
            float v = 0.0f;
            if (row < RNK)             v = A[row * DIN + col];
            else if (row < RNK + NEXP) v = router_w[(row - RNK) * DIN + col];
            __half h = __float2half_rn(v);
            g_Ah[idx] = h;
            g_Al[idx] = __float2half_rn(v - __half2float(h));
        } else {
            int j = idx - n1;
            int o = j / K2DIM;
            int er = j - o * K2DIM;
            int e = er >> 6, r = er & 63;
            float v = SCALING * B[((size_t)e * DOUT + o) * RNK + r];
            g_B2h[j] = __float2half_rn(v);
        }
    }
}

// ---------------- routing: softmax/top-2 -> dense G (fp16) ----------------
__global__ void route_kernel(int T)
{
    int warp = (blockIdx.x * blockDim.x + threadIdx.x) >> 5;
    int lane = threadIdx.x & 31;
    if (warp >= T) return;

    const float* h = g_H + (size_t)warp * 128;

    float logit = (lane < NEXP) ? h[64 + lane] : -1e30f;
    float m = logit;
    #pragma unroll
    for (int off = 16; off; off >>= 1)
        m = fmaxf(m, __shfl_xor_sync(0xffffffffu, m, off));
    float p = (lane < NEXP) ? expf(logit - m) : 0.0f;
    float s = p;
    #pragma unroll
    for (int off = 16; off; off >>= 1)
        s += __shfl_xor_sync(0xffffffffu, s, off);
    p /= s;

    float v1 = p; int i1 = lane;
    #pragma unroll
    for (int off = 16; off; off >>= 1) {
        float ov = __shfl_xor_sync(0xffffffffu, v1, off);
        int   oi = __shfl_xor_sync(0xffffffffu, i1, off);
        if (ov > v1 || (ov == v1 && oi < i1)) { v1 = ov; i1 = oi; }
    }
    float v2 = (lane == i1) ? -1.0f : p; int i2 = lane;
    #pragma unroll
    for (int off = 16; off; off >>= 1) {
        float ov = __shfl_xor_sync(0xffffffffu, v2, off);
        int   oi = __shfl_xor_sync(0xffffffffu, i2, off);
        if (ov > v2 || (ov == v2 && oi < i2)) { v2 = ov; i2 = oi; }
    }

    float snorm = v1 + v2 + 1e-6f;
    float w0 = v1 / snorm, w1 = v2 / snorm;

    __half* Gh = g_Gh + (size_t)warp * K2DIM;
    for (int j = lane; j < K2DIM; j += 32) {
        int e = j >> 6, r = j & 63;
        float val = 0.0f;
        if (e == i1)      val = w0 * h[r];
        else if (e == i2) val = w1 * h[r];
        Gh[j] = __float2half_rn(val);
    }
}

// ---------------------------------------------------------------------------
extern "C" void kernel_launch(void* const* d_in, const int* in_sizes, int n_in,
                              void* d_out, int out_size)
{
    const float* x        = (const float*)d_in[0];
    const float* base_w   = (const float*)d_in[1];
    const float* base_b   = (const float*)d_in[2];
    const float* A        = (const float*)d_in[3];
    const float* B        = (const float*)d_in[4];
    const float* router_w = (const float*)d_in[5];
    float* out = (float*)d_out;

    const int T = in_sizes[0] / DIN;    // 8192

    __half *dXh, *dWh, *dWl, *dAh, *dAl, *dGh, *dB2h;
    float* dH;
    cudaGetSymbolAddress((void**)&dXh,  g_Xh);
    cudaGetSymbolAddress((void**)&dWh,  g_Wh);
    cudaGetSymbolAddress((void**)&dWl,  g_Wl);
    cudaGetSymbolAddress((void**)&dAh,  g_Ah);
    cudaGetSymbolAddress((void**)&dAl,  g_Al);
    cudaGetSymbolAddress((void**)&dGh,  g_Gh);
    cudaGetSymbolAddress((void**)&dB2h, g_B2h);
    cudaGetSymbolAddress((void**)&dH,   g_H);

    const int smem3 = 3 * 2 * 128 * RSB;     // 110592
    cudaFuncSetAttribute(gemm_hmma,    cudaFuncAttributeMaxDynamicSharedMemorySize, smem3);
    cudaFuncSetAttribute(gemm_hmma_ks, cudaFuncAttributeMaxDynamicSharedMemorySize, smem3);

    // 1) conversions: X -> hi only; W -> hi+lo; Acat hi/lo + B2 hi
    conv_hi<<<1024, 256>>>(x,      dXh, T * DIN / 4);
    conv_hl<<<1024, 256>>>(base_w, dWh, dWl, DOUT * DIN / 4);
    prep2_kernel<<<1024, 256>>>(A, router_w, B);

    // 2) H = Xh @ (Ah + Al)^T  (2-term fp16), split-K -> atomicAdd
    cudaMemsetAsync(dH, 0, (size_t)T * 128 * sizeof(float));
    {
        SegList SL;
        SL.s[0] = { dXh, dAh, DIN / 64, DIN, DIN };
        SL.s[1] = { dXh, dAl, DIN / 64, DIN, DIN };
        dim3 grid(4, T / 128);
        gemm_hmma_ks<<<grid, 256, smem3>>>(SL, dH, 128);
    }

    // 3) routing -> dense G (fp16)
    route_kernel<<<(T + 7) / 8, 256>>>(T);

    // 4) out = Xh@(Wh+Wl)^T + Gh@B2h^T + bias   (3 segments, K=9216)
    {
        SegList SL;
        SL.s[0] = { dXh, dWh, DIN / 64,   DIN,   DIN };
        SL.s[1] = { dXh, dWl, DIN / 64,   DIN,   DIN };
        SL.s[2] = { dGh, dB2h, K2DIM / 64, K2DIM, K2DIM };
        dim3 grid(DOUT / 128, T / 128);
        gemm_hmma<<<grid, 256, smem3>>>(SL, 3, base_b, out, DOUT);
    }
}